// round 14
// baseline (speedup 1.0000x reference)
#include <cuda_runtime.h>
#include <cuda_fp16.h>
#include <cstdint>

// UVRGCNLayer: N=50000 nodes, E=600000 edges, D=128, R=500
#define DIM    128
#define NMAX   50176        // 196*256: unguarded GEMM loads
#define RMAX   500
#define CAP    64
#define MTR    256          // GEMM CTA M tile (rows)

// ---- scratch (device globals; no allocation allowed) ----
__device__ int   g_deg[NMAX];
__device__ __align__(16) int g_bin[(size_t)NMAX * CAP];  // packed (src | etype<<17)
__device__ __align__(16) unsigned char g_Bimg[65536];    // fp16 B fragments
// permuted fp16 rows: 32 uint2 per row; pos p -> kp = (p>>3)*8 + ((p&7)>>1) + (p&1)*4
__device__ __align__(16) uint2 g_Ah[(size_t)NMAX * 32];    // h, permuted fp16
__device__ __align__(16) uint2 g_Aagg[(size_t)NMAX * 32];  // norm*agg, permuted fp16
__device__ __align__(16) uint2 g_emb16[(size_t)RMAX * 32]; // emb, permuted fp16

// B image: [kstep][nhalf][reggroup][lane] x 16B
#define IMGOFF(ks, wc, rg, l) \
    (((((ks) * 2 + (wc)) * 4 + (rg)) * 32 + (l)) * 16)
// per-CTA smem (n-quarter fixed): [kstep][rg2][lane] x 16B  (16 KB)
#define SMOFFQ(ks, rg2, l) \
    ((((ks) * 2 + (rg2)) * 32 + (l)) * 16)

__device__ __forceinline__ void mma16816(float* c, const uint32_t* a,
                                         uint32_t b0, uint32_t b1)
{
    asm volatile(
        "mma.sync.aligned.m16n8k16.row.col.f32.f16.f16.f32 "
        "{%0,%1,%2,%3}, {%4,%5,%6,%7}, {%8,%9}, {%0,%1,%2,%3};"
        : "+f"(c[0]), "+f"(c[1]), "+f"(c[2]), "+f"(c[3])
        : "r"(a[0]), "r"(a[1]), "r"(a[2]), "r"(a[3]), "r"(b0), "r"(b1));
}

__device__ __forceinline__ uint2 ldcg2(const uint2* p)
{
    uint2 v;
    asm volatile("ld.global.cg.v2.u32 {%0,%1}, [%2];"
                 : "=r"(v.x), "=r"(v.y) : "l"(p));
    return v;
}

__device__ __forceinline__ uint32_t h2pack(float a, float b)
{
    __half2 p = __floats2half2_rn(a, b);
    return *(uint32_t*)&p;
}

// Convert two permuted uint2 slots (c, c+1) of one row into a uint4.
__device__ __forceinline__ uint4 cvt_pair(const float2* row, int c)
{
    int kp0 = (c >> 2) * 8 + (c & 3);
    int kp1 = ((c + 1) >> 2) * 8 + ((c + 1) & 3);
    float2 v0 = __ldg(row + kp0);
    float2 v1 = __ldg(row + kp0 + 4);
    float2 v2 = __ldg(row + kp1);
    float2 v3 = __ldg(row + kp1 + 4);
    return make_uint4(h2pack(v0.x, v0.y), h2pack(v1.x, v1.y),
                      h2pack(v2.x, v2.y), h2pack(v3.x, v3.y));
}

// ===================== fused front kernel (R12 form) =====================
#define HBLK  (NMAX / 16)    // 3136
#define BBLK  8
#define EMBLK 32

__global__ __launch_bounds__(256)
void front_kernel(const int* __restrict__ src, const int* __restrict__ dst,
                  const int* __restrict__ etype, int* __restrict__ deg,
                  int* __restrict__ bin,
                  const float* __restrict__ h, const float* __restrict__ emb,
                  const float* __restrict__ Wn, const float* __restrict__ Wl,
                  uint2* __restrict__ Ah, uint2* __restrict__ emb16,
                  unsigned char* __restrict__ bimg, int E, int N, int eblk)
{
    int bid = blockIdx.x, tid = threadIdx.x;

    if (bid < eblk) {                    // ---- edge binning ----
        int i = bid * 256 + tid;
        if (i >= E) return;
        int d = __ldg(dst + i);
        int pos = atomicAdd(deg + d, 1);
        if (pos < CAP)
            bin[(size_t)d * CAP + pos] = __ldg(src + i) | (__ldg(etype + i) << 17);
        return;
    }
    bid -= eblk;

    if (bid < HBLK) {                    // ---- h -> permuted fp16 ----
        int idx = bid * 256 + tid;       // row*16 + c2
        int row = idx >> 4, c2 = idx & 15;
        uint4* dst4 = (uint4*)(Ah + (size_t)row * 32 + c2 * 2);
        if (row < N) {
            *dst4 = cvt_pair((const float2*)(h + (size_t)row * DIM), c2 * 2);
        } else {
            *dst4 = make_uint4(0u, 0u, 0u, 0u);
        }
        return;
    }
    bid -= HBLK;

    if (bid < BBLK) {                    // ---- B fragments (fp16) ----
        int g = bid * 256 + tid;
        #pragma unroll
        for (int q = 0; q < 2; q++) {
            int gg = g * 2 + q;          // 0..4095
            int lane = gg & 31;
            int rg   = (gg >> 5) & 3;
            int wc   = (gg >> 7) & 1;
            int ks   = gg >> 8;
            int gid  = lane >> 2;
            int tig  = lane & 3;
            uint32_t bf[4];
            #pragma unroll
            for (int j = 0; j < 4; j++) {
                int r    = rg * 4 + j;
                int f    = r >> 1;
                int half = r & 1;
                int n    = wc * 64 + f * 8 + gid;
                int kg   = ks * 16 + half * 8 + tig * 2;
                float w0, w1;
                if (kg < 128) {
                    w0 = __ldg(Wn + kg * DIM + n);
                    w1 = __ldg(Wn + (kg + 1) * DIM + n);
                } else {
                    w0 = __ldg(Wl + (kg - 128) * DIM + n);
                    w1 = __ldg(Wl + (kg - 127) * DIM + n);
                }
                bf[j] = h2pack(w0, w1);
            }
            *(uint4*)(bimg + IMGOFF(ks, wc, rg, lane)) = *(uint4*)bf;
        }
        return;
    }
    bid -= BBLK;

    {                                    // ---- emb -> permuted fp16 ----
        int idx = bid * 256 + tid;
        if (idx >= RMAX * 16) return;
        int r = idx >> 4, c2 = idx & 15;
        uint4* dst4 = (uint4*)(emb16 + (size_t)r * 32 + c2 * 2);
        *dst4 = cvt_pair((const float2*)(emb + (size_t)r * DIM), c2 * 2);
    }
}

// ===================== aggregation (R12 form) =====================
__device__ __forceinline__ void acc_h2(float4& acc, uint2 hv, uint2 ev)
{
    float2 f0 = __half22float2(*(__half2*)&hv.x);
    float2 f1 = __half22float2(*(__half2*)&hv.y);
    float2 e0 = __half22float2(*(__half2*)&ev.x);
    float2 e1 = __half22float2(*(__half2*)&ev.y);
    acc.x += f0.x + e0.x; acc.y += f0.y + e0.y;
    acc.z += f1.x + e1.x; acc.w += f1.y + e1.y;
}

__global__ __launch_bounds__(256)
void agg_gather(const uint2* __restrict__ h16, const uint2* __restrict__ emb16,
                const int* __restrict__ bin, const int* __restrict__ deg,
                const float* __restrict__ norm, uint2* __restrict__ aagg,
                const float* __restrict__ We, float* __restrict__ out, int N)
{
    int r = blockIdx.x * 8 + (threadIdx.x >> 5);
    int lane = threadIdx.x & 31;
    if (r >= N) return;

    const int* b = bin + (size_t)r * CAP;
    int n = __ldg(deg + r);
    if (n > CAP) n = CAP;

    if (n == 0) {
        // rare (~e^-12): agg = 0; out[r] = relu(h[r] @ We) in fp32
        aagg[(size_t)r * 32 + lane] = make_uint2(0u, 0u);
        float4 acc = make_float4(0.f, 0.f, 0.f, 0.f);
        const uint2* hr = h16 + (size_t)r * 32;
        for (int c = 0; c < 32; c++) {
            uint2 hv = __ldg(hr + c);
            int kp0 = (c >> 2) * 8 + (c & 3);
            float2 f0 = __half22float2(*(__half2*)&hv.x);
            float2 f1 = __half22float2(*(__half2*)&hv.y);
            int k0 = kp0 * 2, k1 = (kp0 + 4) * 2;
            float4 w;
            w = __ldg((const float4*)&We[k0 * DIM + lane * 4]);
            acc.x = fmaf(f0.x, w.x, acc.x); acc.y = fmaf(f0.x, w.y, acc.y);
            acc.z = fmaf(f0.x, w.z, acc.z); acc.w = fmaf(f0.x, w.w, acc.w);
            w = __ldg((const float4*)&We[(k0 + 1) * DIM + lane * 4]);
            acc.x = fmaf(f0.y, w.x, acc.x); acc.y = fmaf(f0.y, w.y, acc.y);
            acc.z = fmaf(f0.y, w.z, acc.z); acc.w = fmaf(f0.y, w.w, acc.w);
            w = __ldg((const float4*)&We[k1 * DIM + lane * 4]);
            acc.x = fmaf(f1.x, w.x, acc.x); acc.y = fmaf(f1.x, w.y, acc.y);
            acc.z = fmaf(f1.x, w.z, acc.z); acc.w = fmaf(f1.x, w.w, acc.w);
            w = __ldg((const float4*)&We[(k1 + 1) * DIM + lane * 4]);
            acc.x = fmaf(f1.y, w.x, acc.x); acc.y = fmaf(f1.y, w.y, acc.y);
            acc.z = fmaf(f1.y, w.z, acc.z); acc.w = fmaf(f1.y, w.w, acc.w);
        }
        acc.x = fmaxf(acc.x, 0.f); acc.y = fmaxf(acc.y, 0.f);
        acc.z = fmaxf(acc.z, 0.f); acc.w = fmaxf(acc.w, 0.f);
        ((float4*)out)[(size_t)r * 32 + lane] = acc;
        return;
    }

    float4 acc = make_float4(0.f, 0.f, 0.f, 0.f);
    int j = 0;
    for (; j + 4 <= n; j += 4) {
        int4 v = __ldg((const int4*)(b + j));       // 4 edge descriptors, 1 load
        uint2 h0 = ldcg2(&h16[(size_t)(v.x & 0x1FFFF) * 32 + lane]);
        uint2 e0 = __ldg(&emb16[(size_t)((unsigned)v.x >> 17) * 32 + lane]);
        uint2 h1 = ldcg2(&h16[(size_t)(v.y & 0x1FFFF) * 32 + lane]);
        uint2 e1 = __ldg(&emb16[(size_t)((unsigned)v.y >> 17) * 32 + lane]);
        uint2 h2 = ldcg2(&h16[(size_t)(v.z & 0x1FFFF) * 32 + lane]);
        uint2 e2 = __ldg(&emb16[(size_t)((unsigned)v.z >> 17) * 32 + lane]);
        uint2 h3 = ldcg2(&h16[(size_t)(v.w & 0x1FFFF) * 32 + lane]);
        uint2 e3 = __ldg(&emb16[(size_t)((unsigned)v.w >> 17) * 32 + lane]);
        acc_h2(acc, h0, e0);
        acc_h2(acc, h1, e1);
        acc_h2(acc, h2, e2);
        acc_h2(acc, h3, e3);
    }
    for (; j < n; j++) {
        int v = __ldg(b + j);
        uint2 hv = ldcg2(&h16[(size_t)(v & 0x1FFFF) * 32 + lane]);
        uint2 ev = __ldg(&emb16[(size_t)((unsigned)v >> 17) * 32 + lane]);
        acc_h2(acc, hv, ev);
    }
    float nv = __ldg(norm + r);
    uint2 o;
    o.x = h2pack(acc.x * nv, acc.y * nv);
    o.y = h2pack(acc.z * nv, acc.w * nv);
    aagg[(size_t)r * 32 + lane] = o;
}

// ===================== HMMA fp16 fused GEMM, N-quartered (3 CTA/SM) ==========
// CTA tile 256 x 32 (blockIdx.y = N-quarter); 8 warps, warp tile 32x32.
// A: Aagg rows (ks<8) then Ah rows (ks>=8), permuted fp16. 8 mma / ks / warp.
__global__ __launch_bounds__(256, 3)
void gemm_mma(const uint2* __restrict__ Aagg, const uint2* __restrict__ Ah,
              const int* __restrict__ deg, const unsigned char* __restrict__ bimg,
              float* __restrict__ out, int Nn)
{
    extern __shared__ unsigned char smem[];

    const int tid  = threadIdx.x;
    const int wid  = tid >> 5;          // warp 0..7, 32 rows each
    const int lane = tid & 31;
    const int wq   = blockIdx.y;        // N quarter 0..3
    const int gid  = lane >> 2;
    const int tig  = lane & 3;

    // stage this N-quarter's B fragments (16 KB)
    {
        const int half = wq >> 1;
        const int rp   = (wq & 1) * 2;
        const uint4* src = (const uint4*)bimg;
        uint4* dst = (uint4*)smem;
        #pragma unroll
        for (int i = tid; i < 1024; i += 256) {
            int ks = i >> 6, j = i & 63;
            int rg2 = j >> 5, l = j & 31;
            dst[i] = __ldg(src + (((size_t)(ks * 2 + half) * 4 + rp + rg2) * 32 + l));
        }
    }
    __syncthreads();

    const int rowg0 = blockIdx.x * MTR + wid * 32;
    const uint2* pg[2][2];
    const uint2* ph[2][2];
    #pragma unroll
    for (int mf = 0; mf < 2; mf++) {
        int ra = rowg0 + mf * 16 + gid;
        int rb = ra + 8;
        pg[mf][0] = Aagg + (size_t)ra * 32 + tig;
        pg[mf][1] = Aagg + (size_t)rb * 32 + tig;
        ph[mf][0] = Ah   + (size_t)ra * 32 + tig;
        ph[mf][1] = Ah   + (size_t)rb * 32 + tig;
    }

    float acc[2][4][4];
    #pragma unroll
    for (int mf = 0; mf < 2; mf++)
        #pragma unroll
        for (int f = 0; f < 4; f++)
            #pragma unroll
            for (int q = 0; q < 4; q++) acc[mf][f][q] = 0.f;

    uint2 abuf[2][2][2];
    #pragma unroll
    for (int mf = 0; mf < 2; mf++) {
        abuf[0][mf][0] = __ldg(pg[mf][0]);
        abuf[0][mf][1] = __ldg(pg[mf][1]);
    }

    #pragma unroll
    for (int ks = 0; ks < 16; ks++) {
        const int cur = ks & 1;
        if (ks < 15) {
            int ks1 = ks + 1;
            int ko  = (ks1 & 7) * 4;
            #pragma unroll
            for (int mf = 0; mf < 2; mf++) {
                abuf[cur ^ 1][mf][0] = (ks1 < 8) ? __ldg(pg[mf][0] + ko)
                                                 : __ldg(ph[mf][0] + ko);
                abuf[cur ^ 1][mf][1] = (ks1 < 8) ? __ldg(pg[mf][1] + ko)
                                                 : __ldg(ph[mf][1] + ko);
            }
        }

        uint32_t bf[8];
        #pragma unroll
        for (int rg2 = 0; rg2 < 2; rg2++)
            *(uint4*)&bf[rg2 * 4] =
                *(const uint4*)(smem + SMOFFQ(ks, rg2, lane));

        #pragma unroll
        for (int mf = 0; mf < 2; mf++) {
            uint32_t a[4] = {abuf[cur][mf][0].x, abuf[cur][mf][1].x,
                             abuf[cur][mf][0].y, abuf[cur][mf][1].y};
            #pragma unroll
            for (int f = 0; f < 4; f++)
                mma16816(acc[mf][f], a, bf[f * 2], bf[f * 2 + 1]);
        }
    }

    // epilogue: relu + store, skip deg==0 rows (handled by gather)
    #pragma unroll
    for (int mf = 0; mf < 2; mf++) {
        int ra = rowg0 + mf * 16 + gid;
        int rb = ra + 8;
        bool sa = (ra < Nn) && (__ldg(deg + ra) != 0);
        bool sb = (rb < Nn) && (__ldg(deg + rb) != 0);
        #pragma unroll
        for (int f = 0; f < 4; f++) {
            int col = wq * 32 + f * 8 + tig * 2;
            if (sa) {
                float2 o;
                o.x = fmaxf(acc[mf][f][0], 0.f);
                o.y = fmaxf(acc[mf][f][1], 0.f);
                *(float2*)(out + (size_t)ra * DIM + col) = o;
            }
            if (sb) {
                float2 o;
                o.x = fmaxf(acc[mf][f][2], 0.f);
                o.y = fmaxf(acc[mf][f][3], 0.f);
                *(float2*)(out + (size_t)rb * DIM + col) = o;
            }
        }
    }
}

// ---------------------------------------------------------------------------
extern "C" void kernel_launch(void* const* d_in, const int* in_sizes, int n_in,
                              void* d_out, int out_size)
{
    const float* h       = (const float*)d_in[0];
    const float* norm    = (const float*)d_in[1];
    const float* emb_rel = (const float*)d_in[2];
    const float* Wn      = (const float*)d_in[3];
    const float* Wl      = (const float*)d_in[4];
    const float* We      = (const float*)d_in[5];
    const int*   src     = (const int*)d_in[6];
    const int*   dst     = (const int*)d_in[7];
    const int*   etype   = (const int*)d_in[8];
    float*       out     = (float*)d_out;

    const int N = in_sizes[0] / DIM;
    const int E = in_sizes[6];

    int*   deg;   cudaGetSymbolAddress((void**)&deg,   g_deg);
    int*   bin;   cudaGetSymbolAddress((void**)&bin,   g_bin);
    unsigned char* bimg; cudaGetSymbolAddress((void**)&bimg, g_Bimg);
    uint2* ah;    cudaGetSymbolAddress((void**)&ah,    g_Ah);
    uint2* aagg;  cudaGetSymbolAddress((void**)&aagg,  g_Aagg);
    uint2* emb16; cudaGetSymbolAddress((void**)&emb16, g_emb16);

    cudaMemsetAsync(deg, 0, (size_t)N * sizeof(int), 0);

    const int eblk = (E + 255) / 256;
    const int FB = eblk + HBLK + BBLK + EMBLK;
    front_kernel<<<FB, 256>>>(src, dst, etype, deg, bin, h, emb_rel, Wn, Wl,
                              ah, emb16, bimg, E, N, eblk);

    agg_gather<<<(N + 7) / 8, 256>>>(ah, emb16, bin, deg, norm,
                                     aagg, We, out, N);

    const int smem = 16384;
    cudaFuncSetAttribute(gemm_mma, cudaFuncAttributeMaxDynamicSharedMemorySize, smem);
    dim3 grid((N + MTR - 1) / MTR, 4);
    gemm_mma<<<grid, 256, smem>>>(aagg, ah, deg, bimg, out, N);
}

// round 15
// speedup vs baseline: 1.1287x; 1.1287x over previous
#include <cuda_runtime.h>
#include <cuda_fp16.h>
#include <cstdint>

// UVRGCNLayer: N=50000 nodes, E=600000 edges, D=128, R=500
#define DIM    128
#define NMAX   50176        // 196*256: unguarded GEMM loads
#define RMAX   500
#define CAP    64
#define MTR    256          // GEMM CTA M tile (rows)

// ---- scratch (device globals; no allocation allowed) ----
__device__ int   g_deg[NMAX];
__device__ __align__(16) int g_bin[(size_t)NMAX * CAP];  // packed (src | etype<<17)
__device__ __align__(16) unsigned char g_Bimg[65536];    // fp16 B fragments
// unified A image: [row][64] uint2; slots 0..31 = norm*agg (permuted fp16),
// slots 32..63 = h (permuted fp16). slot s(0..31) -> kp = (s>>2)*8+(s&3), pair {kp,kp+4}
__device__ __align__(16) uint2 g_A[(size_t)NMAX * 64];     // 25.7 MB
__device__ __align__(16) uint2 g_emb16[(size_t)RMAX * 32]; // emb, permuted fp16

// B image: [kstep][nhalf][reggroup][lane] x 16B
#define IMGOFF(ks, wc, rg, l) \
    (((((ks) * 2 + (wc)) * 4 + (rg)) * 32 + (l)) * 16)
// per-CTA smem (nhalf fixed): [kstep][reggroup][lane] x 16B  (32 KB)
#define SMOFF(ks, rg, l) \
    ((((ks) * 4 + (rg)) * 32 + (l)) * 16)

__device__ __forceinline__ void mma16816(float* c, const uint32_t* a,
                                         uint32_t b0, uint32_t b1)
{
    asm volatile(
        "mma.sync.aligned.m16n8k16.row.col.f32.f16.f16.f32 "
        "{%0,%1,%2,%3}, {%4,%5,%6,%7}, {%8,%9}, {%0,%1,%2,%3};"
        : "+f"(c[0]), "+f"(c[1]), "+f"(c[2]), "+f"(c[3])
        : "r"(a[0]), "r"(a[1]), "r"(a[2]), "r"(a[3]), "r"(b0), "r"(b1));
}

__device__ __forceinline__ uint2 ldcg2(const uint2* p)
{
    uint2 v;
    asm volatile("ld.global.cg.v2.u32 {%0,%1}, [%2];"
                 : "=r"(v.x), "=r"(v.y) : "l"(p));
    return v;
}

__device__ __forceinline__ uint32_t h2pack(float a, float b)
{
    __half2 p = __floats2half2_rn(a, b);
    return *(uint32_t*)&p;
}

// Convert two permuted slots (c, c+1) of one fp32 row into a uint4.
__device__ __forceinline__ uint4 cvt_pair(const float2* row, int c)
{
    int kp0 = (c >> 2) * 8 + (c & 3);
    int kp1 = ((c + 1) >> 2) * 8 + ((c + 1) & 3);
    float2 v0 = __ldg(row + kp0);
    float2 v1 = __ldg(row + kp0 + 4);
    float2 v2 = __ldg(row + kp1);
    float2 v3 = __ldg(row + kp1 + 4);
    return make_uint4(h2pack(v0.x, v0.y), h2pack(v1.x, v1.y),
                      h2pack(v2.x, v2.y), h2pack(v3.x, v3.y));
}

// ===================== fused front kernel (R12 form) =====================
#define HBLK  (NMAX / 16)    // 3136
#define BBLK  8
#define EMBLK 32

__global__ __launch_bounds__(256)
void front_kernel(const int* __restrict__ src, const int* __restrict__ dst,
                  const int* __restrict__ etype, int* __restrict__ deg,
                  int* __restrict__ bin,
                  const float* __restrict__ h, const float* __restrict__ emb,
                  const float* __restrict__ Wn, const float* __restrict__ Wl,
                  uint2* __restrict__ A, uint2* __restrict__ emb16,
                  unsigned char* __restrict__ bimg, int E, int N, int eblk)
{
    int bid = blockIdx.x, tid = threadIdx.x;

    if (bid < eblk) {                    // ---- edge binning ----
        int i = bid * 256 + tid;
        if (i >= E) return;
        int d = __ldg(dst + i);
        int pos = atomicAdd(deg + d, 1);
        if (pos < CAP)
            bin[(size_t)d * CAP + pos] = __ldg(src + i) | (__ldg(etype + i) << 17);
        return;
    }
    bid -= eblk;

    if (bid < HBLK) {                    // ---- h -> permuted fp16 (A slots 32..63) ----
        int idx = bid * 256 + tid;       // row*16 + c2
        int row = idx >> 4, c2 = idx & 15;
        uint4* dst4 = (uint4*)(A + (size_t)row * 64 + 32 + c2 * 2);
        if (row < N) {
            *dst4 = cvt_pair((const float2*)(h + (size_t)row * DIM), c2 * 2);
        } else {
            *dst4 = make_uint4(0u, 0u, 0u, 0u);
        }
        return;
    }
    bid -= HBLK;

    if (bid < BBLK) {                    // ---- B fragments (fp16) ----
        int g = bid * 256 + tid;
        #pragma unroll
        for (int q = 0; q < 2; q++) {
            int gg = g * 2 + q;          // 0..4095
            int lane = gg & 31;
            int rg   = (gg >> 5) & 3;
            int wc   = (gg >> 7) & 1;
            int ks   = gg >> 8;
            int gid  = lane >> 2;
            int tig  = lane & 3;
            uint32_t bf[4];
            #pragma unroll
            for (int j = 0; j < 4; j++) {
                int r    = rg * 4 + j;
                int f    = r >> 1;
                int half = r & 1;
                int n    = wc * 64 + f * 8 + gid;
                int kg   = ks * 16 + half * 8 + tig * 2;
                float w0, w1;
                if (kg < 128) {
                    w0 = __ldg(Wn + kg * DIM + n);
                    w1 = __ldg(Wn + (kg + 1) * DIM + n);
                } else {
                    w0 = __ldg(Wl + (kg - 128) * DIM + n);
                    w1 = __ldg(Wl + (kg - 127) * DIM + n);
                }
                bf[j] = h2pack(w0, w1);
            }
            *(uint4*)(bimg + IMGOFF(ks, wc, rg, lane)) = *(uint4*)bf;
        }
        return;
    }
    bid -= BBLK;

    {                                    // ---- emb -> permuted fp16 ----
        int idx = bid * 256 + tid;
        if (idx >= RMAX * 16) return;
        int r = idx >> 4, c2 = idx & 15;
        uint4* dst4 = (uint4*)(emb16 + (size_t)r * 32 + c2 * 2);
        *dst4 = cvt_pair((const float2*)(emb + (size_t)r * DIM), c2 * 2);
    }
}

// ===================== aggregation (R12 form, unified A) =====================
__device__ __forceinline__ void acc_h2(float4& acc, uint2 hv, uint2 ev)
{
    float2 f0 = __half22float2(*(__half2*)&hv.x);
    float2 f1 = __half22float2(*(__half2*)&hv.y);
    float2 e0 = __half22float2(*(__half2*)&ev.x);
    float2 e1 = __half22float2(*(__half2*)&ev.y);
    acc.x += f0.x + e0.x; acc.y += f0.y + e0.y;
    acc.z += f1.x + e1.x; acc.w += f1.y + e1.y;
}

__global__ __launch_bounds__(256)
void agg_gather(uint2* __restrict__ A, const uint2* __restrict__ emb16,
                const int* __restrict__ bin, const int* __restrict__ deg,
                const float* __restrict__ norm,
                const float* __restrict__ We, float* __restrict__ out, int N)
{
    int r = blockIdx.x * 8 + (threadIdx.x >> 5);
    int lane = threadIdx.x & 31;
    if (r >= N) return;

    const uint2* h16 = A + 32;           // h half lives at slot offset 32

    const int* b = bin + (size_t)r * CAP;
    int n = __ldg(deg + r);
    if (n > CAP) n = CAP;

    if (n == 0) {
        // rare (~e^-12): agg = 0; out[r] = relu(h[r] @ We) in fp32
        A[(size_t)r * 64 + lane] = make_uint2(0u, 0u);
        float4 acc = make_float4(0.f, 0.f, 0.f, 0.f);
        const uint2* hr = h16 + (size_t)r * 64;
        for (int c = 0; c < 32; c++) {
            uint2 hv = __ldg(hr + c);
            int kp0 = (c >> 2) * 8 + (c & 3);
            float2 f0 = __half22float2(*(__half2*)&hv.x);
            float2 f1 = __half22float2(*(__half2*)&hv.y);
            int k0 = kp0 * 2, k1 = (kp0 + 4) * 2;
            float4 w;
            w = __ldg((const float4*)&We[k0 * DIM + lane * 4]);
            acc.x = fmaf(f0.x, w.x, acc.x); acc.y = fmaf(f0.x, w.y, acc.y);
            acc.z = fmaf(f0.x, w.z, acc.z); acc.w = fmaf(f0.x, w.w, acc.w);
            w = __ldg((const float4*)&We[(k0 + 1) * DIM + lane * 4]);
            acc.x = fmaf(f0.y, w.x, acc.x); acc.y = fmaf(f0.y, w.y, acc.y);
            acc.z = fmaf(f0.y, w.z, acc.z); acc.w = fmaf(f0.y, w.w, acc.w);
            w = __ldg((const float4*)&We[k1 * DIM + lane * 4]);
            acc.x = fmaf(f1.x, w.x, acc.x); acc.y = fmaf(f1.x, w.y, acc.y);
            acc.z = fmaf(f1.x, w.z, acc.z); acc.w = fmaf(f1.x, w.w, acc.w);
            w = __ldg((const float4*)&We[(k1 + 1) * DIM + lane * 4]);
            acc.x = fmaf(f1.y, w.x, acc.x); acc.y = fmaf(f1.y, w.y, acc.y);
            acc.z = fmaf(f1.y, w.z, acc.z); acc.w = fmaf(f1.y, w.w, acc.w);
        }
        acc.x = fmaxf(acc.x, 0.f); acc.y = fmaxf(acc.y, 0.f);
        acc.z = fmaxf(acc.z, 0.f); acc.w = fmaxf(acc.w, 0.f);
        ((float4*)out)[(size_t)r * 32 + lane] = acc;
        return;
    }

    float4 acc = make_float4(0.f, 0.f, 0.f, 0.f);
    int j = 0;
    for (; j + 4 <= n; j += 4) {
        int4 v = __ldg((const int4*)(b + j));       // 4 edge descriptors, 1 load
        uint2 h0 = ldcg2(&h16[(size_t)(v.x & 0x1FFFF) * 64 + lane]);
        uint2 e0 = __ldg(&emb16[(size_t)((unsigned)v.x >> 17) * 32 + lane]);
        uint2 h1 = ldcg2(&h16[(size_t)(v.y & 0x1FFFF) * 64 + lane]);
        uint2 e1 = __ldg(&emb16[(size_t)((unsigned)v.y >> 17) * 32 + lane]);
        uint2 h2 = ldcg2(&h16[(size_t)(v.z & 0x1FFFF) * 64 + lane]);
        uint2 e2 = __ldg(&emb16[(size_t)((unsigned)v.z >> 17) * 32 + lane]);
        uint2 h3 = ldcg2(&h16[(size_t)(v.w & 0x1FFFF) * 64 + lane]);
        uint2 e3 = __ldg(&emb16[(size_t)((unsigned)v.w >> 17) * 32 + lane]);
        acc_h2(acc, h0, e0);
        acc_h2(acc, h1, e1);
        acc_h2(acc, h2, e2);
        acc_h2(acc, h3, e3);
    }
    for (; j < n; j++) {
        int v = __ldg(b + j);
        uint2 hv = ldcg2(&h16[(size_t)(v & 0x1FFFF) * 64 + lane]);
        uint2 ev = __ldg(&emb16[(size_t)((unsigned)v >> 17) * 32 + lane]);
        acc_h2(acc, hv, ev);
    }
    float nv = __ldg(norm + r);
    uint2 o;
    o.x = h2pack(acc.x * nv, acc.y * nv);
    o.y = h2pack(acc.z * nv, acc.w * nv);
    A[(size_t)r * 64 + lane] = o;
}

// ===================== HMMA fp16 single-term fused GEMM =====================
// CTA tile 256 x 64 (blockIdx.y = N-half); 8 warps, warp tile 32x64.
// A: unified image, slots ks*4+tig (0..31 agg, 32..63 h). 16 mma / ks / warp.
__global__ __launch_bounds__(256, 2)
void gemm_mma(const uint2* __restrict__ A,
              const int* __restrict__ deg, const unsigned char* __restrict__ bimg,
              float* __restrict__ out, int Nn)
{
    extern __shared__ unsigned char smem[];

    const int tid  = threadIdx.x;
    const int wid  = tid >> 5;          // warp 0..7, 32 rows each
    const int lane = tid & 31;
    const int wc   = blockIdx.y;        // N half 0..1
    const int gid  = lane >> 2;
    const int tig  = lane & 3;

    // stage this N-half's B fragments (32 KB)
    {
        const uint4* src = (const uint4*)bimg;
        uint4* dst = (uint4*)smem;
        #pragma unroll
        for (int i = tid; i < 2048; i += 256) {
            int ks = i >> 7, j = i & 127;
            dst[i] = __ldg(src + ((size_t)(ks * 2 + wc) * 128 + j));
        }
    }
    __syncthreads();

    const int rowg0 = blockIdx.x * MTR + wid * 32;
    const uint2* pA[2][2];
    #pragma unroll
    for (int mf = 0; mf < 2; mf++) {
        int ra = rowg0 + mf * 16 + gid;
        int rb = ra + 8;
        pA[mf][0] = A + (size_t)ra * 64 + tig;
        pA[mf][1] = A + (size_t)rb * 64 + tig;
    }

    float acc[2][8][4];
    #pragma unroll
    for (int mf = 0; mf < 2; mf++)
        #pragma unroll
        for (int f = 0; f < 8; f++)
            #pragma unroll
            for (int q = 0; q < 4; q++) acc[mf][f][q] = 0.f;

    uint2 abuf[2][2][2];
    #pragma unroll
    for (int mf = 0; mf < 2; mf++) {
        abuf[0][mf][0] = __ldg(pA[mf][0]);
        abuf[0][mf][1] = __ldg(pA[mf][1]);
    }

    #pragma unroll
    for (int ks = 0; ks < 16; ks++) {
        const int cur = ks & 1;
        if (ks < 15) {
            int ko = (ks + 1) * 4;
            #pragma unroll
            for (int mf = 0; mf < 2; mf++) {
                abuf[cur ^ 1][mf][0] = __ldg(pA[mf][0] + ko);
                abuf[cur ^ 1][mf][1] = __ldg(pA[mf][1] + ko);
            }
        }

        #pragma unroll
        for (int nh = 0; nh < 2; nh++) {
            uint32_t bf[8];
            #pragma unroll
            for (int rg = 0; rg < 2; rg++)
                *(uint4*)&bf[rg * 4] =
                    *(const uint4*)(smem + SMOFF(ks, nh * 2 + rg, lane));

            #pragma unroll
            for (int mf = 0; mf < 2; mf++) {
                uint32_t a[4] = {abuf[cur][mf][0].x, abuf[cur][mf][1].x,
                                 abuf[cur][mf][0].y, abuf[cur][mf][1].y};
                #pragma unroll
                for (int f = 0; f < 4; f++)
                    mma16816(acc[mf][nh * 4 + f], a, bf[f * 2], bf[f * 2 + 1]);
            }
        }
    }

    // epilogue: relu + store, skip deg==0 rows (handled by gather)
    #pragma unroll
    for (int mf = 0; mf < 2; mf++) {
        int ra = rowg0 + mf * 16 + gid;
        int rb = ra + 8;
        bool sa = (ra < Nn) && (__ldg(deg + ra) != 0);
        bool sb = (rb < Nn) && (__ldg(deg + rb) != 0);
        #pragma unroll
        for (int f = 0; f < 8; f++) {
            int col = wc * 64 + f * 8 + tig * 2;
            if (sa) {
                float2 o;
                o.x = fmaxf(acc[mf][f][0], 0.f);
                o.y = fmaxf(acc[mf][f][1], 0.f);
                *(float2*)(out + (size_t)ra * DIM + col) = o;
            }
            if (sb) {
                float2 o;
                o.x = fmaxf(acc[mf][f][2], 0.f);
                o.y = fmaxf(acc[mf][f][3], 0.f);
                *(float2*)(out + (size_t)rb * DIM + col) = o;
            }
        }
    }
}

// ---------------------------------------------------------------------------
extern "C" void kernel_launch(void* const* d_in, const int* in_sizes, int n_in,
                              void* d_out, int out_size)
{
    const float* h       = (const float*)d_in[0];
    const float* norm    = (const float*)d_in[1];
    const float* emb_rel = (const float*)d_in[2];
    const float* Wn      = (const float*)d_in[3];
    const float* Wl      = (const float*)d_in[4];
    const float* We      = (const float*)d_in[5];
    const int*   src     = (const int*)d_in[6];
    const int*   dst     = (const int*)d_in[7];
    const int*   etype   = (const int*)d_in[8];
    float*       out     = (float*)d_out;

    const int N = in_sizes[0] / DIM;
    const int E = in_sizes[6];

    int*   deg;   cudaGetSymbolAddress((void**)&deg,   g_deg);
    int*   bin;   cudaGetSymbolAddress((void**)&bin,   g_bin);
    unsigned char* bimg; cudaGetSymbolAddress((void**)&bimg, g_Bimg);
    uint2* A;     cudaGetSymbolAddress((void**)&A,     g_A);
    uint2* emb16; cudaGetSymbolAddress((void**)&emb16, g_emb16);

    cudaMemsetAsync(deg, 0, (size_t)N * sizeof(int), 0);

    const int eblk = (E + 255) / 256;
    const int FB = eblk + HBLK + BBLK + EMBLK;
    front_kernel<<<FB, 256>>>(src, dst, etype, deg, bin, h, emb_rel, Wn, Wl,
                              A, emb16, bimg, E, N, eblk);

    agg_gather<<<(N + 7) / 8, 256>>>(A, emb16, bin, deg, norm, We, out, N);

    const int smem = 32768;
    cudaFuncSetAttribute(gemm_mma, cudaFuncAttributeMaxDynamicSharedMemorySize, smem);
    dim3 grid((N + MTR - 1) / MTR, 2);
    gemm_mma<<<grid, 256, smem>>>(A, deg, bimg, out, N);
}